// round 11
// baseline (speedup 1.0000x reference)
#include <cuda_runtime.h>
#include <cuda_bf16.h>

// x: (128,1,32768) fp32, W: 17 fixed filters (baked as constants), out: (128,17,32768) = relu(conv same)
// PAD_LO=47. Filters 0..5 alternating even-negative K={2,4,8,16,32,64}; 6..11 odd-negative (negation);
// 12..16 piecewise-quadratic bumps, len 1.5K for K=4..64.
//
// R11 = R10 (stcs stores + __launch_bounds__(256,7), bench 47.68) plus two micro-surgeries:
//  (a) __ldcs on the input tile load (read-once stream: evict-first, mirrors the store-side win
//      in the graph-replay steady state),
//  (b) sync3 eliminated: every thread sums raw per-warp totals warpAgg[w < wid] directly
//      (8 broadcast LDS) instead of an 8-thread sub-scan + extra block barrier. Barriers 4 -> 3.

#define NB    128
#define LSEQ  32768
#define NFILT 17
#define TILE  1024
#define NTHR  256
#define NSV   1119          // valid xs elements = TILE + 95
#define NSX   1120

__device__ __forceinline__ float triWeightAbs(int t, int c) {
    // weight of quad filter t (t=0..4 <-> K=4,8,16,32,64) at absolute tap c (0..95); 0 outside support
    const int Ks[5] = {4, 8, 16, 32, 64};
    int K = Ks[t];
    int Lf = K + K / 2;
    int o = 47 - (Lf - 1) / 2;
    int j = c - o;
    if (j < 0 || j >= Lf) return 0.0f;
    int q = K / 4, half = K / 2;
    int s = j / half;
    int u = j - s * half;
    int num = (u < q) ? (u + 1) : (half - u);
    float b = (float)num / (float)q;        // exact: power-of-two denominator
    float w = b * b;
    return (s == 1) ? 2.0f * w : -w;
}

__global__ __launch_bounds__(NTHR, 7)
void Hybrid_block_64175401337035_kernel(const float* __restrict__ x,
                                        float* __restrict__ y) {
    __shared__ __align__(16) float xs[NSX];
    __shared__ __align__(16) float E[NSX];   // E[p] = (-1)^p * sum_{q<p} (-1)^q xs[q]; E[0]=0
    __shared__ float warpAgg[8];             // raw per-warp totals (never overwritten)

    const int tid = threadIdx.x;
    const int n = blockIdx.y;
    const int tileStart = blockIdx.x * TILE;
    const float* xg = x + (size_t)n * LSEQ;

    // ---- load input tile (zero-padded at sequence edges); streaming reads ----
    #pragma unroll
    for (int q = tid; q < NSX; q += NTHR) {
        int g = tileStart - 47 + q;
        xs[q] = (q < NSV && g >= 0 && g < LSEQ) ? __ldcs(xg + g) : 0.0f;
    }
    __syncthreads();                                    // sync 1

    // ---- block scan of (-1)^q xs[q], chunk=5/thread; stride-5 reads are conflict-free ----
    float loc[5];
    float run = 0.0f;
    const int qb = tid * 5;
    #pragma unroll
    for (int j = 0; j < 5; ++j) {
        int q = qb + j;
        float v = 0.0f;
        if (q < NSV) { v = xs[q]; if (q & 1) v = -v; }
        run += v;
        loc[j] = run;
    }
    const unsigned lane = tid & 31;
    const unsigned wid = tid >> 5;
    float inc = run;
    #pragma unroll
    for (int o = 1; o < 32; o <<= 1) {
        float nb = __shfl_up_sync(0xffffffffu, inc, o);
        if (lane >= (unsigned)o) inc += nb;
    }
    if (lane == 31) warpAgg[wid] = inc;                 // warp totals
    __syncthreads();                                    // sync 2

    // block-exclusive prefix: sum raw warp totals below this warp (broadcast LDS, no barrier)
    float pre = inc - run;
    #pragma unroll
    for (int w = 0; w < 7; ++w)
        if ((unsigned)w < wid) pre += warpAgg[w];

    if (tid == 0) E[0] = 0.0f;
    #pragma unroll
    for (int j = 0; j < 5; ++j) {
        int q = qb + j;
        if (q < NSV) {
            float v = pre + loc[j];
            // E[q+1] = (-1)^(q+1) * A[q+1]:  q even -> negative
            E[q + 1] = (q & 1) ? v : -v;
        }
    }
    __syncthreads();                                    // sync 3 (E ready)

    const int xl0 = tid * 4;
    const int i0 = tileStart + xl0;
    float* ybase = y + (size_t)n * NFILT * LSEQ + i0;

    // ---- 12 alternating filters: s(a) = E[a+K]-E[a]; all windows served by 9 aligned LDS.128 ----
    const float4 e16 = *(const float4*)(E + xl0 + 16);
    const float4 e32 = *(const float4*)(E + xl0 + 32);
    const float4 e40 = *(const float4*)(E + xl0 + 40);
    const float4 e44 = *(const float4*)(E + xl0 + 44);
    const float4 e48 = *(const float4*)(E + xl0 + 48);
    const float4 e52 = *(const float4*)(E + xl0 + 52);
    const float4 e56 = *(const float4*)(E + xl0 + 56);
    const float4 e64 = *(const float4*)(E + xl0 + 64);
    const float4 e80 = *(const float4*)(E + xl0 + 80);

    {
        float w0[4], w1[4];
        #define EMIT(kkidx)                                                          \
        {                                                                            \
            float4 ye, yo;                                                           \
            ye.x = fmaxf(w0[0] - w1[0], 0.0f); yo.x = fmaxf(w1[0] - w0[0], 0.0f);    \
            ye.y = fmaxf(w0[1] - w1[1], 0.0f); yo.y = fmaxf(w1[1] - w0[1], 0.0f);    \
            ye.z = fmaxf(w0[2] - w1[2], 0.0f); yo.z = fmaxf(w1[2] - w0[2], 0.0f);    \
            ye.w = fmaxf(w0[3] - w1[3], 0.0f); yo.w = fmaxf(w1[3] - w0[3], 0.0f);    \
            __stcs((float4*)(ybase + (size_t)(kkidx) * LSEQ), ye);                   \
            __stcs((float4*)(ybase + (size_t)(6 + (kkidx)) * LSEQ), yo);             \
        }
        // K=2, o=47: W0 @47, W1 @49
        w0[0]=e44.w; w0[1]=e48.x; w0[2]=e48.y; w0[3]=e48.z;
        w1[0]=e48.y; w1[1]=e48.z; w1[2]=e48.w; w1[3]=e52.x;
        EMIT(0)
        // K=4, o=46: W0 @46, W1 @50
        w0[0]=e44.z; w0[1]=e44.w; w0[2]=e48.x; w0[3]=e48.y;
        w1[0]=e48.z; w1[1]=e48.w; w1[2]=e52.x; w1[3]=e52.y;
        EMIT(1)
        // K=8, o=44: W0 @44, W1 @52
        w0[0]=e44.x; w0[1]=e44.y; w0[2]=e44.z; w0[3]=e44.w;
        w1[0]=e52.x; w1[1]=e52.y; w1[2]=e52.z; w1[3]=e52.w;
        EMIT(2)
        // K=16, o=40: W0 @40, W1 @56
        w0[0]=e40.x; w0[1]=e40.y; w0[2]=e40.z; w0[3]=e40.w;
        w1[0]=e56.x; w1[1]=e56.y; w1[2]=e56.z; w1[3]=e56.w;
        EMIT(3)
        // K=32, o=32: W0 @32, W1 @64
        w0[0]=e32.x; w0[1]=e32.y; w0[2]=e32.z; w0[3]=e32.w;
        w1[0]=e64.x; w1[1]=e64.y; w1[2]=e64.z; w1[3]=e64.w;
        EMIT(4)
        // K=64, o=16: W0 @16, W1 @80
        w0[0]=e16.x; w0[1]=e16.y; w0[2]=e16.z; w0[3]=e16.w;
        w1[0]=e80.x; w1[1]=e80.y; w1[2]=e80.z; w1[3]=e80.w;
        EMIT(5)
        #undef EMIT
    }

    // ---- 5 quadratic filters: fully-unrolled sweep, FFMA-imm, dense LDS.128 ----
    float acc[5][4];
    #pragma unroll
    for (int t = 0; t < 5; ++t)
        #pragma unroll
        for (int pp = 0; pp < 4; ++pp) acc[t][pp] = 0.0f;

    float4 cur = *(const float4*)(xs + xl0);
    #pragma unroll
    for (int m = 0; m < 24; ++m) {
        float4 nxt = *(const float4*)(xs + xl0 + 4 * m + 4);
        float win[8] = {cur.x, cur.y, cur.z, cur.w, nxt.x, nxt.y, nxt.z, nxt.w};
        #pragma unroll
        for (int d = 0; d < 4; ++d) {
            const int c = 4 * m + d;
            #pragma unroll
            for (int t = 0; t < 5; ++t) {
                const float w = triWeightAbs(t, c);
                if (w != 0.0f) {
                    #pragma unroll
                    for (int pp = 0; pp < 4; ++pp)
                        acc[t][pp] = fmaf(w, win[d + pp], acc[t][pp]);
                }
            }
        }
        cur = nxt;
    }
    #pragma unroll
    for (int t = 0; t < 5; ++t) {
        float4 v;
        v.x = fmaxf(acc[t][0], 0.0f);
        v.y = fmaxf(acc[t][1], 0.0f);
        v.z = fmaxf(acc[t][2], 0.0f);
        v.w = fmaxf(acc[t][3], 0.0f);
        __stcs((float4*)(ybase + (size_t)(12 + t) * LSEQ), v);
    }
}

extern "C" void kernel_launch(void* const* d_in, const int* in_sizes, int n_in,
                              void* d_out, int out_size) {
    const float* x = (const float*)d_in[0];
    float* y = (float*)d_out;
    dim3 grid(LSEQ / TILE, NB);
    Hybrid_block_64175401337035_kernel<<<grid, NTHR>>>(x, y);
}

// round 12
// speedup vs baseline: 1.0781x; 1.0781x over previous
#include <cuda_runtime.h>
#include <cuda_bf16.h>

// x: (128,1,32768) fp32, W: 17 fixed filters (baked as constants), out: (128,17,32768) = relu(conv same)
// PAD_LO=47. Filters 0..5 alternating even-negative K={2,4,8,16,32,64}; 6..11 odd-negative (negation);
// 12..16 piecewise-quadratic bumps, len 1.5K for K=4..64.
//
// R12 = R10 (stcs stores + __launch_bounds__(256,7), bench 47.68) + ONLY the sync3 elimination
// from R11 (barriers 4 -> 3; every thread sums raw warp totals directly via broadcast LDS).
// R11's __ldcs on reads is REVERTED: with .cs stores the 17MB input stays L2-resident across
// graph replays (output evicts first), and evict-first reads destroyed that residency
// (bench 47.68 -> 51.26 while single-launch ncu improved — steady-state-only effect).

#define NB    128
#define LSEQ  32768
#define NFILT 17
#define TILE  1024
#define NTHR  256
#define NSV   1119          // valid xs elements = TILE + 95
#define NSX   1120

__device__ __forceinline__ float triWeightAbs(int t, int c) {
    // weight of quad filter t (t=0..4 <-> K=4,8,16,32,64) at absolute tap c (0..95); 0 outside support
    const int Ks[5] = {4, 8, 16, 32, 64};
    int K = Ks[t];
    int Lf = K + K / 2;
    int o = 47 - (Lf - 1) / 2;
    int j = c - o;
    if (j < 0 || j >= Lf) return 0.0f;
    int q = K / 4, half = K / 2;
    int s = j / half;
    int u = j - s * half;
    int num = (u < q) ? (u + 1) : (half - u);
    float b = (float)num / (float)q;        // exact: power-of-two denominator
    float w = b * b;
    return (s == 1) ? 2.0f * w : -w;
}

__global__ __launch_bounds__(NTHR, 7)
void Hybrid_block_64175401337035_kernel(const float* __restrict__ x,
                                        float* __restrict__ y) {
    __shared__ __align__(16) float xs[NSX];
    __shared__ __align__(16) float E[NSX];   // E[p] = (-1)^p * sum_{q<p} (-1)^q xs[q]; E[0]=0
    __shared__ float warpAgg[8];             // raw per-warp totals (never overwritten)

    const int tid = threadIdx.x;
    const int n = blockIdx.y;
    const int tileStart = blockIdx.x * TILE;
    const float* xg = x + (size_t)n * LSEQ;

    // ---- load input tile (zero-padded at sequence edges); DEFAULT cached reads:
    //      with .cs stores, x stays L2-resident across graph replays ----
    #pragma unroll
    for (int q = tid; q < NSX; q += NTHR) {
        int g = tileStart - 47 + q;
        xs[q] = (q < NSV && g >= 0 && g < LSEQ) ? xg[g] : 0.0f;
    }
    __syncthreads();                                    // sync 1

    // ---- block scan of (-1)^q xs[q], chunk=5/thread; stride-5 reads are conflict-free ----
    float loc[5];
    float run = 0.0f;
    const int qb = tid * 5;
    #pragma unroll
    for (int j = 0; j < 5; ++j) {
        int q = qb + j;
        float v = 0.0f;
        if (q < NSV) { v = xs[q]; if (q & 1) v = -v; }
        run += v;
        loc[j] = run;
    }
    const unsigned lane = tid & 31;
    const unsigned wid = tid >> 5;
    float inc = run;
    #pragma unroll
    for (int o = 1; o < 32; o <<= 1) {
        float nb = __shfl_up_sync(0xffffffffu, inc, o);
        if (lane >= (unsigned)o) inc += nb;
    }
    if (lane == 31) warpAgg[wid] = inc;                 // warp totals
    __syncthreads();                                    // sync 2

    // block-exclusive prefix: sum raw warp totals below this warp (broadcast LDS, no barrier)
    float pre = inc - run;
    #pragma unroll
    for (int w = 0; w < 7; ++w)
        if ((unsigned)w < wid) pre += warpAgg[w];

    if (tid == 0) E[0] = 0.0f;
    #pragma unroll
    for (int j = 0; j < 5; ++j) {
        int q = qb + j;
        if (q < NSV) {
            float v = pre + loc[j];
            // E[q+1] = (-1)^(q+1) * A[q+1]:  q even -> negative
            E[q + 1] = (q & 1) ? v : -v;
        }
    }
    __syncthreads();                                    // sync 3 (E ready)

    const int xl0 = tid * 4;
    const int i0 = tileStart + xl0;
    float* ybase = y + (size_t)n * NFILT * LSEQ + i0;

    // ---- 12 alternating filters: s(a) = E[a+K]-E[a]; all windows served by 9 aligned LDS.128 ----
    const float4 e16 = *(const float4*)(E + xl0 + 16);
    const float4 e32 = *(const float4*)(E + xl0 + 32);
    const float4 e40 = *(const float4*)(E + xl0 + 40);
    const float4 e44 = *(const float4*)(E + xl0 + 44);
    const float4 e48 = *(const float4*)(E + xl0 + 48);
    const float4 e52 = *(const float4*)(E + xl0 + 52);
    const float4 e56 = *(const float4*)(E + xl0 + 56);
    const float4 e64 = *(const float4*)(E + xl0 + 64);
    const float4 e80 = *(const float4*)(E + xl0 + 80);

    {
        float w0[4], w1[4];
        #define EMIT(kkidx)                                                          \
        {                                                                            \
            float4 ye, yo;                                                           \
            ye.x = fmaxf(w0[0] - w1[0], 0.0f); yo.x = fmaxf(w1[0] - w0[0], 0.0f);    \
            ye.y = fmaxf(w0[1] - w1[1], 0.0f); yo.y = fmaxf(w1[1] - w0[1], 0.0f);    \
            ye.z = fmaxf(w0[2] - w1[2], 0.0f); yo.z = fmaxf(w1[2] - w0[2], 0.0f);    \
            ye.w = fmaxf(w0[3] - w1[3], 0.0f); yo.w = fmaxf(w1[3] - w0[3], 0.0f);    \
            __stcs((float4*)(ybase + (size_t)(kkidx) * LSEQ), ye);                   \
            __stcs((float4*)(ybase + (size_t)(6 + (kkidx)) * LSEQ), yo);             \
        }
        // K=2, o=47: W0 @47, W1 @49
        w0[0]=e44.w; w0[1]=e48.x; w0[2]=e48.y; w0[3]=e48.z;
        w1[0]=e48.y; w1[1]=e48.z; w1[2]=e48.w; w1[3]=e52.x;
        EMIT(0)
        // K=4, o=46: W0 @46, W1 @50
        w0[0]=e44.z; w0[1]=e44.w; w0[2]=e48.x; w0[3]=e48.y;
        w1[0]=e48.z; w1[1]=e48.w; w1[2]=e52.x; w1[3]=e52.y;
        EMIT(1)
        // K=8, o=44: W0 @44, W1 @52
        w0[0]=e44.x; w0[1]=e44.y; w0[2]=e44.z; w0[3]=e44.w;
        w1[0]=e52.x; w1[1]=e52.y; w1[2]=e52.z; w1[3]=e52.w;
        EMIT(2)
        // K=16, o=40: W0 @40, W1 @56
        w0[0]=e40.x; w0[1]=e40.y; w0[2]=e40.z; w0[3]=e40.w;
        w1[0]=e56.x; w1[1]=e56.y; w1[2]=e56.z; w1[3]=e56.w;
        EMIT(3)
        // K=32, o=32: W0 @32, W1 @64
        w0[0]=e32.x; w0[1]=e32.y; w0[2]=e32.z; w0[3]=e32.w;
        w1[0]=e64.x; w1[1]=e64.y; w1[2]=e64.z; w1[3]=e64.w;
        EMIT(4)
        // K=64, o=16: W0 @16, W1 @80
        w0[0]=e16.x; w0[1]=e16.y; w0[2]=e16.z; w0[3]=e16.w;
        w1[0]=e80.x; w1[1]=e80.y; w1[2]=e80.z; w1[3]=e80.w;
        EMIT(5)
        #undef EMIT
    }

    // ---- 5 quadratic filters: fully-unrolled sweep, FFMA-imm, dense LDS.128 ----
    float acc[5][4];
    #pragma unroll
    for (int t = 0; t < 5; ++t)
        #pragma unroll
        for (int pp = 0; pp < 4; ++pp) acc[t][pp] = 0.0f;

    float4 cur = *(const float4*)(xs + xl0);
    #pragma unroll
    for (int m = 0; m < 24; ++m) {
        float4 nxt = *(const float4*)(xs + xl0 + 4 * m + 4);
        float win[8] = {cur.x, cur.y, cur.z, cur.w, nxt.x, nxt.y, nxt.z, nxt.w};
        #pragma unroll
        for (int d = 0; d < 4; ++d) {
            const int c = 4 * m + d;
            #pragma unroll
            for (int t = 0; t < 5; ++t) {
                const float w = triWeightAbs(t, c);
                if (w != 0.0f) {
                    #pragma unroll
                    for (int pp = 0; pp < 4; ++pp)
                        acc[t][pp] = fmaf(w, win[d + pp], acc[t][pp]);
                }
            }
        }
        cur = nxt;
    }
    #pragma unroll
    for (int t = 0; t < 5; ++t) {
        float4 v;
        v.x = fmaxf(acc[t][0], 0.0f);
        v.y = fmaxf(acc[t][1], 0.0f);
        v.z = fmaxf(acc[t][2], 0.0f);
        v.w = fmaxf(acc[t][3], 0.0f);
        __stcs((float4*)(ybase + (size_t)(12 + t) * LSEQ), v);
    }
}

extern "C" void kernel_launch(void* const* d_in, const int* in_sizes, int n_in,
                              void* d_out, int out_size) {
    const float* x = (const float*)d_in[0];
    float* y = (float*)d_out;
    dim3 grid(LSEQ / TILE, NB);
    Hybrid_block_64175401337035_kernel<<<grid, NTHR>>>(x, y);
}